// round 4
// baseline (speedup 1.0000x reference)
#include <cuda_runtime.h>
#include <cstdint>

#define BATCH 32
#define NTOK  1024
#define DIM   256
#define KNN   8
#define EPSV  1e-8f

#define BM 128
#define BN 128
#define BK 16

typedef unsigned long long u64;

// ---- scratch (static __device__ globals; no allocation allowed) ----
__device__ float g_tn[(size_t)BATCH * NTOK * DIM];          // 32 MB
__device__ float g_sim[(size_t)BATCH * NTOK * NTOK];        // 134 MB
__device__ int   g_topk[BATCH * NTOK * KNN];                // 1 MB

// ---- packed fp32x2 helpers ----
__device__ __forceinline__ u64 pk2(float a) {
    u64 r; asm("mov.b64 %0, {%1, %1};" : "=l"(r) : "f"(a)); return r;
}
__device__ __forceinline__ void fma2(u64& d, u64 a, u64 b) {
    asm("fma.rn.f32x2 %0, %1, %2, %0;" : "+l"(d) : "l"(a), "l"(b));
}
__device__ __forceinline__ void unpk2(float& lo, float& hi, u64 v) {
    asm("mov.b64 {%0, %1}, %2;" : "=f"(lo), "=f"(hi) : "l"(v));
}

// ============================================================
// K1: row-normalize tokens  (one warp per row of 256 floats)
// ============================================================
__global__ void k_normalize(const float* __restrict__ x) {
    int warp = (blockIdx.x * blockDim.x + threadIdx.x) >> 5;
    int lane = threadIdx.x & 31;
    if (warp >= BATCH * NTOK) return;
    const float4* row = (const float4*)(x + (size_t)warp * DIM);
    float4 v0 = row[lane * 2 + 0];
    float4 v1 = row[lane * 2 + 1];
    float s = v0.x * v0.x + v0.y * v0.y + v0.z * v0.z + v0.w * v0.w
            + v1.x * v1.x + v1.y * v1.y + v1.z * v1.z + v1.w * v1.w;
    #pragma unroll
    for (int o = 16; o; o >>= 1) s += __shfl_xor_sync(0xffffffffu, s, o);
    float inv = 1.0f / (sqrtf(s) + EPSV);
    float4* out = (float4*)(g_tn + (size_t)warp * DIM);
    v0.x *= inv; v0.y *= inv; v0.z *= inv; v0.w *= inv;
    v1.x *= inv; v1.y *= inv; v1.z *= inv; v1.w *= inv;
    out[lane * 2 + 0] = v0;
    out[lane * 2 + 1] = v1;
}

// ============================================================
// K2: sim[b] = tn[b] (1024x256) * tn[b]^T  via fp32x2 SGEMM
//   - As2 holds A duplicated (packed-broadcast pairs): LDS.64
//     yields {a,a} directly, no MOVs in inner loop.
//   - Each thread owns cols [tx*4, tx*4+4) and [64+tx*4, 64+tx*4+4):
//     B LDS.64 at 16B stride sweeps all banks -> conflict-floor.
// ============================================================
__global__ __launch_bounds__(256, 2) void k_gemm() {
    __shared__ float As2[BK][2 * BM];   // 16 KB, duplicated pairs
    __shared__ float Bs[BK][BN];        //  8 KB

    const int b       = blockIdx.z;
    const int rowBase = blockIdx.y * BM;
    const int colBase = blockIdx.x * BN;
    const float* __restrict__ A = g_tn + (size_t)b * NTOK * DIM;

    const int tid = threadIdx.x;
    const int tx  = tid & 15;      // col group: cols tx*4 & 64+tx*4
    const int ty  = tid >> 4;      // row group: rows ty*8 .. +7

    // global load mapping: thread -> (row = tid/2, k-sub = (tid&1)*8)
    const int lr = tid >> 1;
    const int lk = (tid & 1) * 8;

    u64 acc[8][4];
    #pragma unroll
    for (int i = 0; i < 8; i++)
        #pragma unroll
        for (int j = 0; j < 4; j++) acc[i][j] = 0ull;

    for (int k0 = 0; k0 < DIM; k0 += BK) {
        const float* ap = A + (size_t)(rowBase + lr) * DIM + k0 + lk;
        const float* bp = A + (size_t)(colBase + lr) * DIM + k0 + lk;
        float4 a0 = *(const float4*)(ap);
        float4 a1 = *(const float4*)(ap + 4);
        float4 b0 = *(const float4*)(bp);
        float4 b1 = *(const float4*)(bp + 4);

        __syncthreads();   // prev compute done before overwriting smem
        // A duplicated: STS.64 of {a,a}
        *(u64*)&As2[lk + 0][2 * lr] = pk2(a0.x);
        *(u64*)&As2[lk + 1][2 * lr] = pk2(a0.y);
        *(u64*)&As2[lk + 2][2 * lr] = pk2(a0.z);
        *(u64*)&As2[lk + 3][2 * lr] = pk2(a0.w);
        *(u64*)&As2[lk + 4][2 * lr] = pk2(a1.x);
        *(u64*)&As2[lk + 5][2 * lr] = pk2(a1.y);
        *(u64*)&As2[lk + 6][2 * lr] = pk2(a1.z);
        *(u64*)&As2[lk + 7][2 * lr] = pk2(a1.w);
        Bs[lk + 0][lr] = b0.x; Bs[lk + 1][lr] = b0.y;
        Bs[lk + 2][lr] = b0.z; Bs[lk + 3][lr] = b0.w;
        Bs[lk + 4][lr] = b1.x; Bs[lk + 5][lr] = b1.y;
        Bs[lk + 6][lr] = b1.z; Bs[lk + 7][lr] = b1.w;
        __syncthreads();

        #pragma unroll
        for (int kk = 0; kk < BK; kk++) {
            u64 bq0 = *(const u64*)&Bs[kk][tx * 4 + 0];
            u64 bq1 = *(const u64*)&Bs[kk][tx * 4 + 2];
            u64 bq2 = *(const u64*)&Bs[kk][64 + tx * 4 + 0];
            u64 bq3 = *(const u64*)&Bs[kk][64 + tx * 4 + 2];
            #pragma unroll
            for (int i = 0; i < 8; i++) {
                u64 ap2 = *(const u64*)&As2[kk][2 * (ty * 8 + i)];
                fma2(acc[i][0], ap2, bq0);
                fma2(acc[i][1], ap2, bq1);
                fma2(acc[i][2], ap2, bq2);
                fma2(acc[i][3], ap2, bq3);
            }
        }
    }

    float* C = g_sim + (size_t)b * NTOK * NTOK;
    #pragma unroll
    for (int i = 0; i < 8; i++) {
        int r = rowBase + ty * 8 + i;
        float o0, o1, o2, o3, o4, o5, o6, o7;
        unpk2(o0, o1, acc[i][0]);
        unpk2(o2, o3, acc[i][1]);
        unpk2(o4, o5, acc[i][2]);
        unpk2(o6, o7, acc[i][3]);
        float* dst = C + (size_t)r * NTOK + colBase;
        *(float4*)(dst + tx * 4)      = make_float4(o0, o1, o2, o3);
        *(float4*)(dst + 64 + tx * 4) = make_float4(o4, o5, o6, o7);
    }
}

// ============================================================
// K3: top-8 per row (one warp / row): lane-local sorted-8,
//     then 8-round tournament merge across lanes.
// ============================================================
__global__ void k_topk() {
    int gr   = (blockIdx.x * blockDim.x + threadIdx.x) >> 5;
    int lane = threadIdx.x & 31;
    if (gr >= BATCH * NTOK) return;
    int n = gr & (NTOK - 1);
    const float* __restrict__ row = g_sim + (size_t)gr * NTOK;

    float val[KNN];
    int   idx[KNN];
    #pragma unroll
    for (int i = 0; i < KNN; i++) { val[i] = -3.4e38f; idx[i] = -1; }

    #pragma unroll 4
    for (int i = 0; i < NTOK / 32; i++) {
        int j = lane + i * 32;
        float v = row[j];
        if (j == n) v = -3.4e38f;          // mask self
        if (v > val[KNN - 1]) {
            val[KNN - 1] = v; idx[KNN - 1] = j;
            #pragma unroll
            for (int p = KNN - 1; p > 0; --p) {
                if (val[p] > val[p - 1]) {
                    float tv = val[p]; val[p] = val[p - 1]; val[p - 1] = tv;
                    int   ti = idx[p]; idx[p] = idx[p - 1]; idx[p - 1] = ti;
                }
            }
        }
    }

    int ptr = 0;
    #pragma unroll
    for (int t = 0; t < KNN; t++) {
        float hv = (ptr < KNN) ? val[ptr] : -3.4e38f;
        int   hj = (ptr < KNN) ? idx[ptr] : -1;
        float bv = hv; int bl = lane;
        #pragma unroll
        for (int off = 16; off; off >>= 1) {
            float ov = __shfl_down_sync(0xffffffffu, bv, off);
            int   ol = __shfl_down_sync(0xffffffffu, bl, off);
            if (ov > bv) { bv = ov; bl = ol; }
        }
        bl = __shfl_sync(0xffffffffu, bl, 0);          // broadcast winner lane
        int bj = __shfl_sync(0xffffffffu, hj, bl);     // winner's index
        if (lane == 0) g_topk[gr * KNN + t] = bj;
        if (lane == bl) ptr++;
    }
}

// ============================================================
// K4: zero output
// ============================================================
__global__ void k_zero(float4* __restrict__ out, int n4) {
    int i      = blockIdx.x * blockDim.x + threadIdx.x;
    int stride = gridDim.x * blockDim.x;
    for (; i < n4; i += stride) out[i] = make_float4(0.f, 0.f, 0.f, 0.f);
}

// ============================================================
// K5: mutual-kNN edge scatter (one thread per (row, t))
// ============================================================
__global__ void k_mutual(float* __restrict__ out) {
    int e = blockIdx.x * blockDim.x + threadIdx.x;
    if (e >= BATCH * NTOK * KNN) return;
    int gr = e >> 3;            // global row
    int t  = e & 7;
    int b  = gr >> 10;
    int n  = gr & (NTOK - 1);
    int j  = g_topk[gr * KNN + t];
    const int* tj = g_topk + ((b << 10) + j) * KNN;
    bool mutual = false;
    #pragma unroll
    for (int s = 0; s < KNN; s++) mutual |= (tj[s] == n);
    if (mutual)
        out[((size_t)b << 20) + ((size_t)n << 10) + (size_t)j] = 1.0f;
}

// ============================================================
extern "C" void kernel_launch(void* const* d_in, const int* in_sizes, int n_in,
                              void* d_out, int out_size) {
    const float* tokens = (const float*)d_in[0];
    float* out = (float*)d_out;

    // K1: 8 rows per 256-thread block
    k_normalize<<<BATCH * NTOK / 8, 256>>>(tokens);

    // K2: 8x8 tiles per batch
    dim3 gg(NTOK / BN, NTOK / BM, BATCH);
    k_gemm<<<gg, 256>>>();

    // K3: 8 warps per block, one row each
    k_topk<<<BATCH * NTOK / 8, 256>>>();

    // K4: zero 134 MB output
    k_zero<<<2048, 256>>>((float4*)out, BATCH * NTOK * NTOK / 4);

    // K5: mutual edges
    k_mutual<<<(BATCH * NTOK * KNN + 255) / 256, 256>>>(out);
}

// round 5
// speedup vs baseline: 2.1189x; 2.1189x over previous
#include <cuda_runtime.h>
#include <cstdint>

#define BATCH 32
#define NTOK  1024
#define DIM   256
#define KNN   8
#define EPSV  1e-8f

#define BM 128
#define BN 128
#define BK 16

typedef unsigned long long u64;

// ---- scratch (static __device__ globals; no allocation allowed) ----
__device__ float g_tn[(size_t)BATCH * NTOK * DIM];          // 32 MB
__device__ float g_sim[(size_t)BATCH * NTOK * NTOK];        // 134 MB
__device__ int   g_topk[BATCH * NTOK * KNN];                // 1 MB

// ---- packed fp32x2 helpers (FFMA2: 2x fp32 FMA per issue on sm_103a) ----
__device__ __forceinline__ u64 pk2(float a) {
    u64 r; asm("mov.b64 %0, {%1, %1};" : "=l"(r) : "f"(a)); return r;
}
__device__ __forceinline__ void fma2(u64& d, u64 a, u64 b) {
    asm("fma.rn.f32x2 %0, %1, %2, %0;" : "+l"(d) : "l"(a), "l"(b));
}
__device__ __forceinline__ void unpk2(float& lo, float& hi, u64 v) {
    asm("mov.b64 {%0, %1}, %2;" : "=f"(lo), "=f"(hi) : "l"(v));
}

// ============================================================
// K1: row-normalize tokens  (one warp per row of 256 floats)
// ============================================================
__global__ void k_normalize(const float* __restrict__ x) {
    int warp = (blockIdx.x * blockDim.x + threadIdx.x) >> 5;
    int lane = threadIdx.x & 31;
    if (warp >= BATCH * NTOK) return;
    const float4* row = (const float4*)(x + (size_t)warp * DIM);
    float4 v0 = row[lane * 2 + 0];
    float4 v1 = row[lane * 2 + 1];
    float s = v0.x * v0.x + v0.y * v0.y + v0.z * v0.z + v0.w * v0.w
            + v1.x * v1.x + v1.y * v1.y + v1.z * v1.z + v1.w * v1.w;
    #pragma unroll
    for (int o = 16; o; o >>= 1) s += __shfl_xor_sync(0xffffffffu, s, o);
    float inv = 1.0f / (sqrtf(s) + EPSV);
    float4* out = (float4*)(g_tn + (size_t)warp * DIM);
    v0.x *= inv; v0.y *= inv; v0.z *= inv; v0.w *= inv;
    v1.x *= inv; v1.y *= inv; v1.z *= inv; v1.w *= inv;
    out[lane * 2 + 0] = v0;
    out[lane * 2 + 1] = v1;
}

// ============================================================
// K2: sim[b] = tn[b] * tn[b]^T, SYMMETRIC: only the 36
//     upper-triangular 128x128 tile-pairs are computed.
//     Inner loop is the proven round-3 v1 schedule (untouched).
//     Off-diagonal tiles also mirror-store C[c][r] via STG.128.
// ============================================================
__global__ __launch_bounds__(256, 2) void k_gemm() {
    __shared__ float As[BK][BM];
    __shared__ float Bs[BK][BN];

    // decode triangular tile pair: rowTile ti <= colTile tj
    int t = blockIdx.x;
    int ti = 0;
    while (t >= 8 - ti) { t -= 8 - ti; ti++; }
    const int tj = ti + t;

    const int b       = blockIdx.z;
    const int rowBase = ti * BM;
    const int colBase = tj * BN;
    const float* __restrict__ A = g_tn + (size_t)b * NTOK * DIM;

    const int tid = threadIdx.x;
    const int tx  = tid & 15;      // 0..15 -> 8 cols each
    const int ty  = tid >> 4;      // 0..15 -> 8 rows each

    // global load mapping: thread -> (row = tid/2, k-sub = (tid&1)*8)
    const int lr = tid >> 1;
    const int lk = (tid & 1) * 8;

    u64 acc[8][4];
    #pragma unroll
    for (int i = 0; i < 8; i++)
        #pragma unroll
        for (int j = 0; j < 4; j++) acc[i][j] = 0ull;

    for (int k0 = 0; k0 < DIM; k0 += BK) {
        const float* ap = A + (size_t)(rowBase + lr) * DIM + k0 + lk;
        const float* bp = A + (size_t)(colBase + lr) * DIM + k0 + lk;
        float4 a0 = *(const float4*)(ap);
        float4 a1 = *(const float4*)(ap + 4);
        float4 b0 = *(const float4*)(bp);
        float4 b1 = *(const float4*)(bp + 4);

        __syncthreads();   // prev compute done before overwriting smem
        As[lk + 0][lr] = a0.x; As[lk + 1][lr] = a0.y;
        As[lk + 2][lr] = a0.z; As[lk + 3][lr] = a0.w;
        As[lk + 4][lr] = a1.x; As[lk + 5][lr] = a1.y;
        As[lk + 6][lr] = a1.z; As[lk + 7][lr] = a1.w;
        Bs[lk + 0][lr] = b0.x; Bs[lk + 1][lr] = b0.y;
        Bs[lk + 2][lr] = b0.z; Bs[lk + 3][lr] = b0.w;
        Bs[lk + 4][lr] = b1.x; Bs[lk + 5][lr] = b1.y;
        Bs[lk + 6][lr] = b1.z; Bs[lk + 7][lr] = b1.w;
        __syncthreads();

        #pragma unroll
        for (int kk = 0; kk < BK; kk++) {
            float4 av0 = *(const float4*)&As[kk][ty * 8];
            float4 av1 = *(const float4*)&As[kk][ty * 8 + 4];
            u64 bp0 = *(const u64*)&Bs[kk][tx * 8 + 0];
            u64 bp1 = *(const u64*)&Bs[kk][tx * 8 + 2];
            u64 bp2 = *(const u64*)&Bs[kk][tx * 8 + 4];
            u64 bp3 = *(const u64*)&Bs[kk][tx * 8 + 6];
            u64 p;
            p = pk2(av0.x); fma2(acc[0][0],p,bp0); fma2(acc[0][1],p,bp1); fma2(acc[0][2],p,bp2); fma2(acc[0][3],p,bp3);
            p = pk2(av0.y); fma2(acc[1][0],p,bp0); fma2(acc[1][1],p,bp1); fma2(acc[1][2],p,bp2); fma2(acc[1][3],p,bp3);
            p = pk2(av0.z); fma2(acc[2][0],p,bp0); fma2(acc[2][1],p,bp1); fma2(acc[2][2],p,bp2); fma2(acc[2][3],p,bp3);
            p = pk2(av0.w); fma2(acc[3][0],p,bp0); fma2(acc[3][1],p,bp1); fma2(acc[3][2],p,bp2); fma2(acc[3][3],p,bp3);
            p = pk2(av1.x); fma2(acc[4][0],p,bp0); fma2(acc[4][1],p,bp1); fma2(acc[4][2],p,bp2); fma2(acc[4][3],p,bp3);
            p = pk2(av1.y); fma2(acc[5][0],p,bp0); fma2(acc[5][1],p,bp1); fma2(acc[5][2],p,bp2); fma2(acc[5][3],p,bp3);
            p = pk2(av1.z); fma2(acc[6][0],p,bp0); fma2(acc[6][1],p,bp1); fma2(acc[6][2],p,bp2); fma2(acc[6][3],p,bp3);
            p = pk2(av1.w); fma2(acc[7][0],p,bp0); fma2(acc[7][1],p,bp1); fma2(acc[7][2],p,bp2); fma2(acc[7][3],p,bp3);
        }
    }

    float* C = g_sim + (size_t)b * NTOK * NTOK;

    // unpack 8x8 micro-tile to scalars
    float v[8][8];
    #pragma unroll
    for (int i = 0; i < 8; i++) {
        unpk2(v[i][0], v[i][1], acc[i][0]);
        unpk2(v[i][2], v[i][3], acc[i][1]);
        unpk2(v[i][4], v[i][5], acc[i][2]);
        unpk2(v[i][6], v[i][7], acc[i][3]);
    }

    // normal store: C[rowBase+ty*8+i][colBase+tx*8 ..+8]
    #pragma unroll
    for (int i = 0; i < 8; i++) {
        float* dst = C + (size_t)(rowBase + ty * 8 + i) * NTOK + colBase + tx * 8;
        *(float4*)(dst)     = make_float4(v[i][0], v[i][1], v[i][2], v[i][3]);
        *(float4*)(dst + 4) = make_float4(v[i][4], v[i][5], v[i][6], v[i][7]);
    }

    // mirror store for off-diagonal tiles: C[colBase+tx*8+j][rowBase+ty*8 ..+8]
    if (ti != tj) {
        #pragma unroll
        for (int j = 0; j < 8; j++) {
            float* dst = C + (size_t)(colBase + tx * 8 + j) * NTOK + rowBase + ty * 8;
            *(float4*)(dst)     = make_float4(v[0][j], v[1][j], v[2][j], v[3][j]);
            *(float4*)(dst + 4) = make_float4(v[4][j], v[5][j], v[6][j], v[7][j]);
        }
    }
}

// ============================================================
// K3: top-8 per row (one warp / row): lane-local sorted-8,
//     then 8-round tournament merge across lanes.
// ============================================================
__global__ void k_topk() {
    int gr   = (blockIdx.x * blockDim.x + threadIdx.x) >> 5;
    int lane = threadIdx.x & 31;
    if (gr >= BATCH * NTOK) return;
    int n = gr & (NTOK - 1);
    const float* __restrict__ row = g_sim + (size_t)gr * NTOK;

    float val[KNN];
    int   idx[KNN];
    #pragma unroll
    for (int i = 0; i < KNN; i++) { val[i] = -3.4e38f; idx[i] = -1; }

    #pragma unroll 4
    for (int i = 0; i < NTOK / 32; i++) {
        int j = lane + i * 32;
        float v = row[j];
        if (j == n) v = -3.4e38f;          // mask self
        if (v > val[KNN - 1]) {
            val[KNN - 1] = v; idx[KNN - 1] = j;
            #pragma unroll
            for (int p = KNN - 1; p > 0; --p) {
                if (val[p] > val[p - 1]) {
                    float tv = val[p]; val[p] = val[p - 1]; val[p - 1] = tv;
                    int   ti = idx[p]; idx[p] = idx[p - 1]; idx[p - 1] = ti;
                }
            }
        }
    }

    int ptr = 0;
    #pragma unroll
    for (int t = 0; t < KNN; t++) {
        float hv = (ptr < KNN) ? val[ptr] : -3.4e38f;
        int   hj = (ptr < KNN) ? idx[ptr] : -1;
        float bv = hv; int bl = lane;
        #pragma unroll
        for (int off = 16; off; off >>= 1) {
            float ov = __shfl_down_sync(0xffffffffu, bv, off);
            int   ol = __shfl_down_sync(0xffffffffu, bl, off);
            if (ov > bv) { bv = ov; bl = ol; }
        }
        bl = __shfl_sync(0xffffffffu, bl, 0);          // broadcast winner lane
        int bj = __shfl_sync(0xffffffffu, hj, bl);     // winner's index
        if (lane == 0) g_topk[gr * KNN + t] = bj;
        if (lane == bl) ptr++;
    }
}

// ============================================================
// K4: zero output
// ============================================================
__global__ void k_zero(float4* __restrict__ out, int n4) {
    int i      = blockIdx.x * blockDim.x + threadIdx.x;
    int stride = gridDim.x * blockDim.x;
    for (; i < n4; i += stride) out[i] = make_float4(0.f, 0.f, 0.f, 0.f);
}

// ============================================================
// K5: mutual-kNN edge scatter (one thread per (row, t))
// ============================================================
__global__ void k_mutual(float* __restrict__ out) {
    int e = blockIdx.x * blockDim.x + threadIdx.x;
    if (e >= BATCH * NTOK * KNN) return;
    int gr = e >> 3;            // global row
    int t  = e & 7;
    int b  = gr >> 10;
    int n  = gr & (NTOK - 1);
    int j  = g_topk[gr * KNN + t];
    const int* tj = g_topk + ((b << 10) + j) * KNN;
    bool mutual = false;
    #pragma unroll
    for (int s = 0; s < KNN; s++) mutual |= (tj[s] == n);
    if (mutual)
        out[((size_t)b << 20) + ((size_t)n << 10) + (size_t)j] = 1.0f;
}

// ============================================================
extern "C" void kernel_launch(void* const* d_in, const int* in_sizes, int n_in,
                              void* d_out, int out_size) {
    const float* tokens = (const float*)d_in[0];
    float* out = (float*)d_out;

    // K1: 8 rows per 256-thread block
    k_normalize<<<BATCH * NTOK / 8, 256>>>(tokens);

    // K2: 36 triangular tile-pairs per batch
    dim3 gg(36, 1, BATCH);
    k_gemm<<<gg, 256>>>();

    // K3: 8 warps per block, one row each
    k_topk<<<BATCH * NTOK / 8, 256>>>();

    // K4: zero 134 MB output
    k_zero<<<2048, 256>>>((float4*)out, BATCH * NTOK * NTOK / 4);

    // K5: mutual edges
    k_mutual<<<(BATCH * NTOK * KNN + 255) / 256, 256>>>(out);
}

// round 6
// speedup vs baseline: 2.2670x; 1.0699x over previous
#include <cuda_runtime.h>
#include <cstdint>

#define BATCH 32
#define NTOK  1024
#define DIM   256
#define KNN   8
#define EPSV  1e-8f

#define BM 128
#define BN 128
#define BK 16

typedef unsigned long long u64;

// ---- scratch (static __device__ globals; no allocation allowed) ----
__device__ float g_tn[(size_t)BATCH * NTOK * DIM];          // 32 MB
__device__ float g_sim[(size_t)BATCH * NTOK * NTOK];        // 134 MB
__device__ int   g_topk[BATCH * NTOK * KNN];                // 1 MB

// ---- packed fp32x2 helpers (FFMA2: 2x fp32 FMA per issue on sm_103a) ----
__device__ __forceinline__ u64 pk2(float a) {
    u64 r; asm("mov.b64 %0, {%1, %1};" : "=l"(r) : "f"(a)); return r;
}
__device__ __forceinline__ void fma2(u64& d, u64 a, u64 b) {
    asm("fma.rn.f32x2 %0, %1, %2, %0;" : "+l"(d) : "l"(a), "l"(b));
}
__device__ __forceinline__ void unpk2(float& lo, float& hi, u64 v) {
    asm("mov.b64 {%0, %1}, %2;" : "=f"(lo), "=f"(hi) : "l"(v));
}

// ============================================================
// K1: row-normalize tokens  (one warp per row of 256 floats)
// ============================================================
__global__ void k_normalize(const float* __restrict__ x) {
    int warp = (blockIdx.x * blockDim.x + threadIdx.x) >> 5;
    int lane = threadIdx.x & 31;
    if (warp >= BATCH * NTOK) return;
    const float4* row = (const float4*)(x + (size_t)warp * DIM);
    float4 v0 = row[lane * 2 + 0];
    float4 v1 = row[lane * 2 + 1];
    float s = v0.x * v0.x + v0.y * v0.y + v0.z * v0.z + v0.w * v0.w
            + v1.x * v1.x + v1.y * v1.y + v1.z * v1.z + v1.w * v1.w;
    #pragma unroll
    for (int o = 16; o; o >>= 1) s += __shfl_xor_sync(0xffffffffu, s, o);
    float inv = 1.0f / (sqrtf(s) + EPSV);
    float4* out = (float4*)(g_tn + (size_t)warp * DIM);
    v0.x *= inv; v0.y *= inv; v0.z *= inv; v0.w *= inv;
    v1.x *= inv; v1.y *= inv; v1.z *= inv; v1.w *= inv;
    out[lane * 2 + 0] = v0;
    out[lane * 2 + 1] = v1;
}

// ============================================================
// K2: sim[b] = tn[b] * tn[b]^T, SYMMETRIC (36 tile-pairs).
//   v1 schedule (front-batched loads -> 32 FFMA2), but B columns
//   split into [tx*4, +4) and [64+tx*4, +4): 16B lane stride
//   -> conflict-free LDS.64 (2-phase floor) instead of 4-way.
// ============================================================
__global__ __launch_bounds__(256, 2) void k_gemm() {
    __shared__ float As[BK][BM];
    __shared__ float Bs[BK][BN];

    // decode triangular tile pair: rowTile ti <= colTile tj
    int t = blockIdx.x;
    int ti = 0;
    while (t >= 8 - ti) { t -= 8 - ti; ti++; }
    const int tj = ti + t;

    const int b       = blockIdx.z;
    const int rowBase = ti * BM;
    const int colBase = tj * BN;
    const float* __restrict__ A = g_tn + (size_t)b * NTOK * DIM;

    const int tid = threadIdx.x;
    const int tx  = tid & 15;      // col groups: tx*4 and 64+tx*4
    const int ty  = tid >> 4;      // rows ty*8 .. +7

    // global load mapping: thread -> (row = tid/2, k-sub = (tid&1)*8)
    const int lr = tid >> 1;
    const int lk = (tid & 1) * 8;

    u64 acc[8][4];
    #pragma unroll
    for (int i = 0; i < 8; i++)
        #pragma unroll
        for (int j = 0; j < 4; j++) acc[i][j] = 0ull;

    for (int k0 = 0; k0 < DIM; k0 += BK) {
        const float* ap = A + (size_t)(rowBase + lr) * DIM + k0 + lk;
        const float* bp = A + (size_t)(colBase + lr) * DIM + k0 + lk;
        float4 a0 = *(const float4*)(ap);
        float4 a1 = *(const float4*)(ap + 4);
        float4 b0 = *(const float4*)(bp);
        float4 b1 = *(const float4*)(bp + 4);

        __syncthreads();   // prev compute done before overwriting smem
        As[lk + 0][lr] = a0.x; As[lk + 1][lr] = a0.y;
        As[lk + 2][lr] = a0.z; As[lk + 3][lr] = a0.w;
        As[lk + 4][lr] = a1.x; As[lk + 5][lr] = a1.y;
        As[lk + 6][lr] = a1.z; As[lk + 7][lr] = a1.w;
        Bs[lk + 0][lr] = b0.x; Bs[lk + 1][lr] = b0.y;
        Bs[lk + 2][lr] = b0.z; Bs[lk + 3][lr] = b0.w;
        Bs[lk + 4][lr] = b1.x; Bs[lk + 5][lr] = b1.y;
        Bs[lk + 6][lr] = b1.z; Bs[lk + 7][lr] = b1.w;
        __syncthreads();

        #pragma unroll
        for (int kk = 0; kk < BK; kk++) {
            float4 av0 = *(const float4*)&As[kk][ty * 8];
            float4 av1 = *(const float4*)&As[kk][ty * 8 + 4];
            u64 bp0 = *(const u64*)&Bs[kk][tx * 4 + 0];
            u64 bp1 = *(const u64*)&Bs[kk][tx * 4 + 2];
            u64 bp2 = *(const u64*)&Bs[kk][64 + tx * 4 + 0];
            u64 bp3 = *(const u64*)&Bs[kk][64 + tx * 4 + 2];
            u64 p;
            p = pk2(av0.x); fma2(acc[0][0],p,bp0); fma2(acc[0][1],p,bp1); fma2(acc[0][2],p,bp2); fma2(acc[0][3],p,bp3);
            p = pk2(av0.y); fma2(acc[1][0],p,bp0); fma2(acc[1][1],p,bp1); fma2(acc[1][2],p,bp2); fma2(acc[1][3],p,bp3);
            p = pk2(av0.z); fma2(acc[2][0],p,bp0); fma2(acc[2][1],p,bp1); fma2(acc[2][2],p,bp2); fma2(acc[2][3],p,bp3);
            p = pk2(av0.w); fma2(acc[3][0],p,bp0); fma2(acc[3][1],p,bp1); fma2(acc[3][2],p,bp2); fma2(acc[3][3],p,bp3);
            p = pk2(av1.x); fma2(acc[4][0],p,bp0); fma2(acc[4][1],p,bp1); fma2(acc[4][2],p,bp2); fma2(acc[4][3],p,bp3);
            p = pk2(av1.y); fma2(acc[5][0],p,bp0); fma2(acc[5][1],p,bp1); fma2(acc[5][2],p,bp2); fma2(acc[5][3],p,bp3);
            p = pk2(av1.z); fma2(acc[6][0],p,bp0); fma2(acc[6][1],p,bp1); fma2(acc[6][2],p,bp2); fma2(acc[6][3],p,bp3);
            p = pk2(av1.w); fma2(acc[7][0],p,bp0); fma2(acc[7][1],p,bp1); fma2(acc[7][2],p,bp2); fma2(acc[7][3],p,bp3);
        }
    }

    float* C = g_sim + (size_t)b * NTOK * NTOK;

    // unpack 8x8 micro-tile: v[i][0..3] -> cols tx*4.., v[i][4..7] -> cols 64+tx*4..
    float v[8][8];
    #pragma unroll
    for (int i = 0; i < 8; i++) {
        unpk2(v[i][0], v[i][1], acc[i][0]);
        unpk2(v[i][2], v[i][3], acc[i][1]);
        unpk2(v[i][4], v[i][5], acc[i][2]);
        unpk2(v[i][6], v[i][7], acc[i][3]);
    }

    // normal store
    #pragma unroll
    for (int i = 0; i < 8; i++) {
        float* dst = C + (size_t)(rowBase + ty * 8 + i) * NTOK + colBase;
        *(float4*)(dst + tx * 4)      = make_float4(v[i][0], v[i][1], v[i][2], v[i][3]);
        *(float4*)(dst + 64 + tx * 4) = make_float4(v[i][4], v[i][5], v[i][6], v[i][7]);
    }

    // mirror store for off-diagonal tiles: C[col][row block]
    if (ti != tj) {
        #pragma unroll
        for (int j = 0; j < 8; j++) {
            int cj = (j < 4) ? (tx * 4 + j) : (64 + tx * 4 + (j - 4));
            float* dst = C + (size_t)(colBase + cj) * NTOK + rowBase + ty * 8;
            *(float4*)(dst)     = make_float4(v[0][j], v[1][j], v[2][j], v[3][j]);
            *(float4*)(dst + 4) = make_float4(v[4][j], v[5][j], v[6][j], v[7][j]);
        }
    }
}

// ============================================================
// K3: top-8 per row (one warp / row): lane-local sorted-8,
//     then 8-round tournament merge across lanes.
// ============================================================
__global__ void k_topk() {
    int gr   = (blockIdx.x * blockDim.x + threadIdx.x) >> 5;
    int lane = threadIdx.x & 31;
    if (gr >= BATCH * NTOK) return;
    int n = gr & (NTOK - 1);
    const float* __restrict__ row = g_sim + (size_t)gr * NTOK;

    float val[KNN];
    int   idx[KNN];
    #pragma unroll
    for (int i = 0; i < KNN; i++) { val[i] = -3.4e38f; idx[i] = -1; }

    #pragma unroll 4
    for (int i = 0; i < NTOK / 32; i++) {
        int j = lane + i * 32;
        float v = row[j];
        if (j == n) v = -3.4e38f;          // mask self
        if (v > val[KNN - 1]) {
            val[KNN - 1] = v; idx[KNN - 1] = j;
            #pragma unroll
            for (int p = KNN - 1; p > 0; --p) {
                if (val[p] > val[p - 1]) {
                    float tv = val[p]; val[p] = val[p - 1]; val[p - 1] = tv;
                    int   ti = idx[p]; idx[p] = idx[p - 1]; idx[p - 1] = ti;
                }
            }
        }
    }

    int ptr = 0;
    #pragma unroll
    for (int t = 0; t < KNN; t++) {
        float hv = (ptr < KNN) ? val[ptr] : -3.4e38f;
        int   hj = (ptr < KNN) ? idx[ptr] : -1;
        float bv = hv; int bl = lane;
        #pragma unroll
        for (int off = 16; off; off >>= 1) {
            float ov = __shfl_down_sync(0xffffffffu, bv, off);
            int   ol = __shfl_down_sync(0xffffffffu, bl, off);
            if (ov > bv) { bv = ov; bl = ol; }
        }
        bl = __shfl_sync(0xffffffffu, bl, 0);          // broadcast winner lane
        int bj = __shfl_sync(0xffffffffu, hj, bl);     // winner's index
        if (lane == 0) g_topk[gr * KNN + t] = bj;
        if (lane == bl) ptr++;
    }
}

// ============================================================
// K4: zero output
// ============================================================
__global__ void k_zero(float4* __restrict__ out, int n4) {
    int i      = blockIdx.x * blockDim.x + threadIdx.x;
    int stride = gridDim.x * blockDim.x;
    for (; i < n4; i += stride) out[i] = make_float4(0.f, 0.f, 0.f, 0.f);
}

// ============================================================
// K5: mutual-kNN edge scatter (one thread per (row, t))
// ============================================================
__global__ void k_mutual(float* __restrict__ out) {
    int e = blockIdx.x * blockDim.x + threadIdx.x;
    if (e >= BATCH * NTOK * KNN) return;
    int gr = e >> 3;            // global row
    int t  = e & 7;
    int b  = gr >> 10;
    int n  = gr & (NTOK - 1);
    int j  = g_topk[gr * KNN + t];
    const int* tj = g_topk + ((b << 10) + j) * KNN;
    bool mutual = false;
    #pragma unroll
    for (int s = 0; s < KNN; s++) mutual |= (tj[s] == n);
    if (mutual)
        out[((size_t)b << 20) + ((size_t)n << 10) + (size_t)j] = 1.0f;
}

// ============================================================
extern "C" void kernel_launch(void* const* d_in, const int* in_sizes, int n_in,
                              void* d_out, int out_size) {
    const float* tokens = (const float*)d_in[0];
    float* out = (float*)d_out;

    // K1: 8 rows per 256-thread block
    k_normalize<<<BATCH * NTOK / 8, 256>>>(tokens);

    // K2: 36 triangular tile-pairs per batch
    dim3 gg(36, 1, BATCH);
    k_gemm<<<gg, 256>>>();

    // K3: 8 warps per block, one row each
    k_topk<<<BATCH * NTOK / 8, 256>>>();

    // K4: zero 134 MB output
    k_zero<<<2048, 256>>>((float4*)out, BATCH * NTOK * NTOK / 4);

    // K5: mutual edges
    k_mutual<<<(BATCH * NTOK * KNN + 255) / 256, 256>>>(out);
}